// round 15
// baseline (speedup 1.0000x reference)
#include <cuda_runtime.h>
#include <cuda_bf16.h>
#include <cstdint>

// Problem shape: A [64, 2048, 64], B [64, 64, 2048], out [64, 2048, 2048] (batch=4*16 flattened)
#define NBATCH 64
#define SDIM   2048
#define TDIM   2048
#define DDIM   64
#define NA_EL  (NBATCH * SDIM * DDIM)   // 8388608
#define NB_EL  (NBATCH * DDIM * TDIM)   // 8388608
#define MM_BLOCKS 1024                  // minmax blocks per tensor
#define NGROUPS 2048                    // super-groups: (b, m-tile, n-half), 8 tiles each
#define GEMM_GRID 296                   // 2 CTAs per SM (148 SMs)

// ---- device-global state (scratch; no allocations allowed) ----
__device__ float g_pmin[2][MM_BLOCKS], g_pmax[2][MM_BLOCKS];
__device__ float g_scale, g_dA, g_zA;
__device__ __nv_bfloat16 g_Bq[NB_EL];

// ---- pass 1: per-tensor min/max partials (deterministic, no atomics, no reset) ----
// Exactly 8 grid-stride steps per thread -> fully unrolled for 8-deep LDG MLP.
__global__ void __launch_bounds__(256) k_minmax(const float* __restrict__ A,
                                               const float* __restrict__ B) {
    const int sel = blockIdx.z;
    const float4* x4 = (const float4*)(sel ? B : A);
    const int base = blockIdx.x * blockDim.x + threadIdx.x;
    const int stride = MM_BLOCKS * 256;           // n4 / stride == 8 exactly
    float4 v[8];
    #pragma unroll
    for (int j = 0; j < 8; j++) v[j] = x4[base + j * stride];
    float vmin = 0.0f, vmax = 0.0f;
    #pragma unroll
    for (int j = 0; j < 8; j++) {
        vmin = fminf(vmin, fminf(fminf(v[j].x, v[j].y), fminf(v[j].z, v[j].w)));
        vmax = fmaxf(vmax, fmaxf(fmaxf(v[j].x, v[j].y), fmaxf(v[j].z, v[j].w)));
    }
    #pragma unroll
    for (int o = 16; o > 0; o >>= 1) {
        vmin = fminf(vmin, __shfl_xor_sync(0xffffffffu, vmin, o));
        vmax = fmaxf(vmax, __shfl_xor_sync(0xffffffffu, vmax, o));
    }
    __shared__ float smin[8], smax[8];
    int wid = threadIdx.x >> 5, lane = threadIdx.x & 31;
    if (lane == 0) { smin[wid] = vmin; smax[wid] = vmax; }
    __syncthreads();
    if (threadIdx.x == 0) {
        float m = smin[0], M = smax[0];
        #pragma unroll
        for (int w = 1; w < 8; w++) { m = fminf(m, smin[w]); M = fmaxf(M, smax[w]); }
        g_pmin[sel][blockIdx.x] = m;
        g_pmax[sel][blockIdx.x] = M;
    }
}

// ---- pass 2: params (recomputed per block; deterministic) + fake-quant of B ONLY.
// A is quantized on the fly inside the GEMM (it is reused 8x per group, so the
// f32->int-bf16 conversion is amortized; this halves the quant pass traffic).
__global__ void __launch_bounds__(256) k_quant(const float* __restrict__ B) {
    const int t = threadIdx.x;
    float mA =  1e30f, MA = -1e30f, mB =  1e30f, MB = -1e30f;
    #pragma unroll
    for (int j = 0; j < MM_BLOCKS / 256; j++) {
        int idx = t + j * 256;
        mA = fminf(mA, g_pmin[0][idx]); MA = fmaxf(MA, g_pmax[0][idx]);
        mB = fminf(mB, g_pmin[1][idx]); MB = fmaxf(MB, g_pmax[1][idx]);
    }
    #pragma unroll
    for (int o = 16; o > 0; o >>= 1) {
        mA = fminf(mA, __shfl_xor_sync(0xffffffffu, mA, o));
        MA = fmaxf(MA, __shfl_xor_sync(0xffffffffu, MA, o));
        mB = fminf(mB, __shfl_xor_sync(0xffffffffu, mB, o));
        MB = fmaxf(MB, __shfl_xor_sync(0xffffffffu, MB, o));
    }
    __shared__ float sred[4][8];
    __shared__ float s_delta, s_zp;
    int wid = t >> 5, lane = t & 31;
    if (lane == 0) { sred[0][wid] = mA; sred[1][wid] = MA; sred[2][wid] = mB; sred[3][wid] = MB; }
    __syncthreads();
    if (t == 0) {
        float minA = sred[0][0], maxA = sred[1][0], minB = sred[2][0], maxB = sred[3][0];
        #pragma unroll
        for (int w = 1; w < 8; w++) {
            minA = fminf(minA, sred[0][w]); maxA = fmaxf(maxA, sred[1][w]);
            minB = fminf(minB, sred[2][w]); maxB = fmaxf(maxB, sred[3][w]);
        }
        float dA = fmaxf(__fdiv_rn(maxA - minA, 255.0f), 1e-8f);
        float dB = fmaxf(__fdiv_rn(maxB - minB, 255.0f), 1e-8f);
        s_delta = dB;
        s_zp = rintf(__fdiv_rn(-minB, dB));
        if (blockIdx.x == 0) {
            g_dA = dA;
            g_zA = rintf(__fdiv_rn(-minA, dA));
            g_scale = dA * dB;
        }
    }
    __syncthreads();
    const float delta = s_delta, zp = s_zp;

    const float4* x4 = (const float4*)B;
    uint2* o2 = (uint2*)g_Bq;
    const int n4 = NB_EL / 4;
    #pragma unroll 4
    for (int i = blockIdx.x * blockDim.x + t; i < n4; i += 2048 * 256) {
        float4 v = x4[i];
        float q0 = fminf(fmaxf(rintf(__fdiv_rn(v.x, delta)) + zp, 0.0f), 255.0f) - zp;
        float q1 = fminf(fmaxf(rintf(__fdiv_rn(v.y, delta)) + zp, 0.0f), 255.0f) - zp;
        float q2 = fminf(fmaxf(rintf(__fdiv_rn(v.z, delta)) + zp, 0.0f), 255.0f) - zp;
        float q3 = fminf(fmaxf(rintf(__fdiv_rn(v.w, delta)) + zp, 0.0f), 255.0f) - zp;
        __nv_bfloat162 p0 = __floats2bfloat162_rn(q0, q1);
        __nv_bfloat162 p1 = __floats2bfloat162_rn(q2, q3);
        uint2 u;
        u.x = *(uint32_t*)&p0;
        u.y = *(uint32_t*)&p1;
        o2[i] = u;
    }
}

// ---- pass 3: persistent GEMM, CTA tile 128x128, A-reuse grouping (R13 core) ----
// Super-group u = (b, m, n-half): 8 consecutive n-tiles share one A tile.
// A is cp.async'd as RAW F32 into a staging buffer once per group, then
// quantized smem->smem to integer-bf16 at group start (single sA buffer).
// B keeps the 3-stage prefetch-depth-2 pipeline, single barrier per tile.
#define SA_ROWS 128
#define SA_COLS 72     // 64 + 8 pad (16B row shift -> no LDSM conflicts)
#define SB_ROWS 64
#define SB_COLS 136    // 128 + 8 pad
#define STGF_COLS 68   // f32 staging pitch (rows shift 4 banks)
#define STGF_BYTES (128 * STGF_COLS * 4)       // 34816
#define SA_BYTES (SA_ROWS * SA_COLS * 2)       // 18432
#define SB_BYTES (SB_ROWS * SB_COLS * 2)       // 17408
#define NSTAGE 3
#define SA_OFF  STGF_BYTES
#define SB_OFF  (STGF_BYTES + SA_BYTES)        // 53248
#define SMEM_DYN (SB_OFF + NSTAGE * SB_BYTES)  // 105472 B (2 CTAs/SM)

__device__ __forceinline__ void cpa16(void* dst, const void* src) {
    uint32_t d = (uint32_t)__cvta_generic_to_shared(dst);
    asm volatile("cp.async.cg.shared.global [%0], [%1], 16;" :: "r"(d), "l"(src));
}

__global__ void __launch_bounds__(256, 2) k_gemm(float* __restrict__ out,
                                                 const float* __restrict__ Ain) {
    extern __shared__ char smem_raw[];
    float* stg = (float*)smem_raw;                                 // [128][68] f32
    __nv_bfloat16 (*sA)[SA_COLS] = (__nv_bfloat16 (*)[SA_COLS])(smem_raw + SA_OFF);

    const int tid = threadIdx.x;
    const int bid = blockIdx.x;
    const int warp = tid >> 5, lane = tid & 31;
    const int wm = warp >> 2;      // 0..1 -> 64 rows each
    const int wn = warp & 3;       // 0..3 -> 32 cols each

    const int ar = tid >> 3, ac = (tid & 7) * 8;          // A conv rows ar+{0,32,64,96}
    const int br = tid >> 4, bc = (tid & 15) * 8;         // B rows br+{0,16,32,48}

    auto stageB = [&](int st) -> __nv_bfloat16 (*)[SB_COLS] {
        return (__nv_bfloat16 (*)[SB_COLS])(smem_raw + SB_OFF + st * SB_BYTES);
    };

    // local tile i -> group k = i>>3 (u = bid + k*GRID), j = i&7
    // u decode: b = u>>5, m-tile = (u>>1)&15, n-half = u&1
    const int ngroups = (NGROUPS - bid + GEMM_GRID - 1) / GEMM_GRID;
    const int L = ngroups * 8;

    // commit ONE cp.async group for local tile i: B(i) (+ raw f32 A when i%8==0)
    auto load_group = [&](int i) {
        int k = i >> 3, j = i & 7;
        int u = bid + k * GEMM_GRID;
        int b  = u >> 5;
        int m0 = ((u >> 1) & 15) * 128;
        int n0 = (u & 1) * 1024 + j * 128;
        if ((i & 7) == 0) {
            const float* Af = Ain + (size_t)b * SDIM * DDIM + (size_t)m0 * DDIM;
            // 128 rows x 64 f32 = 2048 16B chunks / 256 threads = 8
            #pragma unroll
            for (int it = 0; it < 8; it++) {
                int id = tid + it * 256;
                int r = id >> 4, cf = (id & 15) * 4;
                cpa16(&stg[r * STGF_COLS + cf], Af + r * DDIM + cf);
            }
        }
        const __nv_bfloat16* Bb = g_Bq + (size_t)b * DDIM * TDIM + n0;
        __nv_bfloat16 (*sB)[SB_COLS] = stageB(i % 3);
        #pragma unroll
        for (int it = 0; it < 4; it++)
            cpa16(&sB[br + it * 16][bc], Bb + (size_t)(br + it * 16) * TDIM + bc);
        asm volatile("cp.async.commit_group;");
    };

    const float s  = g_scale;
    const float dA = g_dA;
    const float zA = g_zA;

    load_group(0);
    if (L > 1) load_group(1);

    for (int i = 0; i < L; i++) {
        if (i + 1 < L) {
            asm volatile("cp.async.wait_group 1;");   // this tile's group done
        } else {
            asm volatile("cp.async.wait_group 0;");
        }
        __syncthreads();   // single barrier per iteration (group-start adds one)

        // group start: quantize staged f32 A -> integer-valued bf16 sA
        if ((i & 7) == 0) {
            #pragma unroll
            for (int it = 0; it < 4; it++) {
                int r = ar + it * 32;
                const float* src = &stg[r * STGF_COLS + ac];
                float4 v0 = *(const float4*)src;
                float4 v1 = *(const float4*)(src + 4);
                float q0 = fminf(fmaxf(rintf(__fdiv_rn(v0.x, dA)) + zA, 0.0f), 255.0f) - zA;
                float q1 = fminf(fmaxf(rintf(__fdiv_rn(v0.y, dA)) + zA, 0.0f), 255.0f) - zA;
                float q2 = fminf(fmaxf(rintf(__fdiv_rn(v0.z, dA)) + zA, 0.0f), 255.0f) - zA;
                float q3 = fminf(fmaxf(rintf(__fdiv_rn(v0.w, dA)) + zA, 0.0f), 255.0f) - zA;
                float q4 = fminf(fmaxf(rintf(__fdiv_rn(v1.x, dA)) + zA, 0.0f), 255.0f) - zA;
                float q5 = fminf(fmaxf(rintf(__fdiv_rn(v1.y, dA)) + zA, 0.0f), 255.0f) - zA;
                float q6 = fminf(fmaxf(rintf(__fdiv_rn(v1.z, dA)) + zA, 0.0f), 255.0f) - zA;
                float q7 = fminf(fmaxf(rintf(__fdiv_rn(v1.w, dA)) + zA, 0.0f), 255.0f) - zA;
                __nv_bfloat162 p0 = __floats2bfloat162_rn(q0, q1);
                __nv_bfloat162 p1 = __floats2bfloat162_rn(q2, q3);
                __nv_bfloat162 p2 = __floats2bfloat162_rn(q4, q5);
                __nv_bfloat162 p3 = __floats2bfloat162_rn(q6, q7);
                uint4 u4;
                u4.x = *(uint32_t*)&p0; u4.y = *(uint32_t*)&p1;
                u4.z = *(uint32_t*)&p2; u4.w = *(uint32_t*)&p3;
                *(uint4*)&sA[r][ac] = u4;
            }
            __syncthreads();   // sA ready before LDSM
        }

        const int k = i >> 3, j = i & 7;
        const int u = bid + k * GEMM_GRID;
        const int b  = u >> 5;
        const int m0 = ((u >> 1) & 15) * 128;
        const int n0 = (u & 1) * 1024 + j * 128;

        __nv_bfloat16 (*sB)[SB_COLS] = stageB(i % 3);

        float acc[4][4][4];
        #pragma unroll
        for (int mi = 0; mi < 4; mi++)
            #pragma unroll
            for (int ni = 0; ni < 4; ni++)
                #pragma unroll
                for (int q = 0; q < 4; q++) acc[mi][ni][q] = 0.0f;

        #pragma unroll
        for (int ks = 0; ks < 4; ks++) {
            const int k0 = ks * 16;
            uint32_t af[4][4];
            #pragma unroll
            for (int mi = 0; mi < 4; mi++) {
                int r = wm * 64 + mi * 16 + (lane & 15);
                int c = k0 + (lane >> 4) * 8;
                uint32_t addr = (uint32_t)__cvta_generic_to_shared(&sA[r][c]);
                asm volatile(
                    "ldmatrix.sync.aligned.m8n8.x4.shared.b16 {%0,%1,%2,%3}, [%4];"
                    : "=r"(af[mi][0]), "=r"(af[mi][1]), "=r"(af[mi][2]), "=r"(af[mi][3])
                    : "r"(addr));
            }
            uint32_t bf[4][2];
            #pragma unroll
            for (int nj = 0; nj < 2; nj++) {
                int r = k0 + (lane & 7) + ((lane >> 3) & 1) * 8;
                int c = wn * 32 + nj * 16 + (lane >> 4) * 8;
                uint32_t addr = (uint32_t)__cvta_generic_to_shared(&sB[r][c]);
                uint32_t t0, t1, t2, t3;
                asm volatile(
                    "ldmatrix.sync.aligned.m8n8.x4.trans.shared.b16 {%0,%1,%2,%3}, [%4];"
                    : "=r"(t0), "=r"(t1), "=r"(t2), "=r"(t3)
                    : "r"(addr));
                bf[nj * 2 + 0][0] = t0; bf[nj * 2 + 0][1] = t1;
                bf[nj * 2 + 1][0] = t2; bf[nj * 2 + 1][1] = t3;
            }
            #pragma unroll
            for (int mi = 0; mi < 4; mi++)
                #pragma unroll
                for (int ni = 0; ni < 4; ni++) {
                    asm volatile(
                        "mma.sync.aligned.m16n8k16.row.col.f32.bf16.bf16.f32 "
                        "{%0,%1,%2,%3}, {%4,%5,%6,%7}, {%8,%9}, {%0,%1,%2,%3};"
                        : "+f"(acc[mi][ni][0]), "+f"(acc[mi][ni][1]),
                          "+f"(acc[mi][ni][2]), "+f"(acc[mi][ni][3])
                        : "r"(af[mi][0]), "r"(af[mi][1]), "r"(af[mi][2]), "r"(af[mi][3]),
                          "r"(bf[ni][0]), "r"(bf[ni][1]));
                }
        }

        // epilogue stores (drain while loads for i+2 stream and next iter computes)
        {
            float* ob = out + (size_t)b * SDIM * TDIM;
            #pragma unroll
            for (int mi = 0; mi < 4; mi++) {
                #pragma unroll
                for (int ni = 0; ni < 4; ni++) {
                    int r = m0 + wm * 64 + mi * 16 + (lane >> 2);
                    int c = n0 + wn * 32 + ni * 8 + (lane & 3) * 2;
                    float2 v0 = make_float2(acc[mi][ni][0] * s, acc[mi][ni][1] * s);
                    float2 v1 = make_float2(acc[mi][ni][2] * s, acc[mi][ni][3] * s);
                    *(float2*)&ob[(size_t)r * TDIM + c]       = v0;
                    *(float2*)&ob[(size_t)(r + 8) * TDIM + c] = v1;
                }
            }
        }

        // prefetch local tile i+2. B stage (i+2)%3 != current/next. Raw-A staging
        // for the next group is refilled only at i%8==6, i.e. AFTER this group's
        // conversion (at i%8==0) consumed it — single staging buffer is safe.
        if (i + 2 < L) load_group(i + 2);
    }
}

extern "C" void kernel_launch(void* const* d_in, const int* in_sizes, int n_in,
                              void* d_out, int out_size) {
    const float* A = (const float*)d_in[0];
    const float* B = (const float*)d_in[1];
    float* out = (float*)d_out;

    cudaFuncSetAttribute(k_gemm, cudaFuncAttributeMaxDynamicSharedMemorySize, SMEM_DYN);

    k_minmax<<<dim3(MM_BLOCKS, 1, 2), 256>>>(A, B);
    k_quant<<<2048, 256>>>(B);
    k_gemm<<<GEMM_GRID, 256, SMEM_DYN>>>(out, A);
}